// round 4
// baseline (speedup 1.0000x reference)
#include <cuda_runtime.h>
#include <cuda_bf16.h>
#include <cstddef>

#define D_IN   128
#define D_OUT  128
#define D_EDGE 32
#define MAX_NODES 100000

// Scratch: per-node precomputed (X_src @ W_src + b) for each relation.
__device__ float g_xwu[(size_t)MAX_NODES * D_OUT];
__device__ float g_xwi[(size_t)MAX_NODES * D_OUT];

// ---------------------------------------------------------------------------
// Packed f32x2 helpers (sm_10x: fma.rn.f32x2 only reachable via PTX).
// ---------------------------------------------------------------------------
__device__ __forceinline__ unsigned long long pk2(float x) {
    unsigned long long r;
    asm("mov.b64 %0, {%1, %1};" : "=l"(r) : "f"(x));
    return r;
}
__device__ __forceinline__ unsigned long long fma2(unsigned long long a,
                                                   unsigned long long b,
                                                   unsigned long long c) {
    unsigned long long d;
    asm("fma.rn.f32x2 %0, %1, %2, %3;" : "=l"(d) : "l"(a), "l"(b), "l"(c));
    return d;
}

union F4U2 { float4 f; ulonglong2 u; };

__device__ __forceinline__ void red_add_v4(float* p, float4 v) {
    asm volatile("red.global.add.v4.f32 [%0], {%1,%2,%3,%4};"
                 :: "l"(p), "f"(v.x), "f"(v.y), "f"(v.z), "f"(v.w)
                 : "memory");
}

// ---------------------------------------------------------------------------
// Node transform v3: PERSISTENT blocks. blockIdx.y picks GEMM (W1->Y1 or
// W2->Y2); W staged ONCE per block; grid-stride over 64-row X tiles.
// Inner loop k-step 4: X broadcast via LDS.128, 32 fma2 per 8 LDS.
// ---------------------------------------------------------------------------
#define NODE_THREADS 512
#define NODE_ROWS    64
#define NODE_SMEM_FLOATS (16384 + 128 + NODE_ROWS * 128)
#define NODE_SMEM_BYTES  (NODE_SMEM_FLOATS * 4)

__global__ __launch_bounds__(NODE_THREADS, 2)
void node_kernel(const float* __restrict__ X,
                 const float* __restrict__ W1, const float* __restrict__ b1,
                 float* __restrict__ Y1,
                 const float* __restrict__ W2, const float* __restrict__ b2,
                 float* __restrict__ Y2,
                 int n)
{
    extern __shared__ float sm[];
    float* Ws = sm;                  // 128*128
    float* bs = sm + 16384;          // 128
    float* Xs = sm + 16512;          // 64 rows * 128

    const float* W = blockIdx.y ? W2 : W1;
    const float* b = blockIdx.y ? b2 : b1;
    float*       Y = blockIdx.y ? Y2 : Y1;

    const int tid = threadIdx.x;

    // Stage weights + bias ONCE per persistent block.
    {
        const float4* Wg = (const float4*)W;
        float4* Wsv = (float4*)Ws;
        #pragma unroll
        for (int i = tid; i < 4096; i += NODE_THREADS) Wsv[i] = Wg[i];
        if (tid < 128) bs[tid] = b[tid];
    }

    const int warp = tid >> 5;
    const int lane = tid & 31;
    const int r0 = warp * 4;          // 16 warps * 4 rows = 64
    const ulonglong2* Wv = (const ulonglong2*)Ws;

    const int ntiles = (n + NODE_ROWS - 1) / NODE_ROWS;

    for (int t = blockIdx.x; t < ntiles; t += gridDim.x) {
        const int row_base = t * NODE_ROWS;
        __syncthreads();   // protect Xs against previous-iteration readers
        {
            const float4* Xg = (const float4*)X;
            float4* Xsv = (float4*)Xs;
            #pragma unroll
            for (int i = tid; i < NODE_ROWS * 32; i += NODE_THREADS) {
                int r = row_base + (i >> 5);
                Xsv[i] = (r < n) ? Xg[(size_t)r * 32 + (i & 31)]
                                 : make_float4(0.f, 0.f, 0.f, 0.f);
            }
        }
        __syncthreads();

        F4U2 bias; bias.f = ((const float4*)bs)[lane];
        ulonglong2 acc[4];
        #pragma unroll
        for (int r = 0; r < 4; r++) acc[r] = bias.u;

        #pragma unroll 2
        for (int k4 = 0; k4 < 32; k4++) {
            const int k0 = 4 * k4;
            ulonglong2 w0 = Wv[(k0 + 0) * 32 + lane];
            ulonglong2 w1 = Wv[(k0 + 1) * 32 + lane];
            ulonglong2 w2 = Wv[(k0 + 2) * 32 + lane];
            ulonglong2 w3 = Wv[(k0 + 3) * 32 + lane];
            #pragma unroll
            for (int r = 0; r < 4; r++) {
                float4 xv = *(const float4*)&Xs[(r0 + r) * 128 + k0]; // LDS.128 bcast
                unsigned long long xa = pk2(xv.x);
                unsigned long long xb = pk2(xv.y);
                unsigned long long xc = pk2(xv.z);
                unsigned long long xd = pk2(xv.w);
                acc[r].x = fma2(xa, w0.x, acc[r].x);
                acc[r].y = fma2(xa, w0.y, acc[r].y);
                acc[r].x = fma2(xb, w1.x, acc[r].x);
                acc[r].y = fma2(xb, w1.y, acc[r].y);
                acc[r].x = fma2(xc, w2.x, acc[r].x);
                acc[r].y = fma2(xc, w2.y, acc[r].y);
                acc[r].x = fma2(xd, w3.x, acc[r].x);
                acc[r].y = fma2(xd, w3.y, acc[r].y);
            }
        }

        #pragma unroll
        for (int r = 0; r < 4; r++) {
            int row = row_base + r0 + r;
            if (row < n) {
                F4U2 o; o.u = acc[r];
                ((float4*)(Y + (size_t)row * 128))[lane] = o.f;
            }
        }
    }
}

// ---------------------------------------------------------------------------
// Relation kernel v4: persistent tiled GEMM, k-step 4 (LDS.128 X broadcast).
//   * W_edge (32x128, 16KB) staged once per block
//   * 64-edge Xe tiles (8KB) + indices staged cooperatively, grid-stride
//   * warp: 8 edges x 4 cols/lane; 64 fma2 per 12 LDS
//   * acc seeded by XW[src] gather (bias folded), relu, red.v4 scatter
// ---------------------------------------------------------------------------
#define REL_THREADS 256
#define REL_TILE 64

__global__ __launch_bounds__(REL_THREADS, 3)
void rel_kernel(const float* __restrict__ XW,
                const float* __restrict__ Xe,
                const int* __restrict__ src,
                const int* __restrict__ dst,
                const float* __restrict__ We,
                float* __restrict__ out,
                int E)
{
    __shared__ float Wes[D_EDGE * D_OUT];       // 16 KB
    __shared__ float Xs[REL_TILE * D_EDGE];     // 8 KB
    __shared__ int   Ss[REL_TILE];
    __shared__ int   Ds[REL_TILE];

    const int tid = threadIdx.x;

    {
        const float4* Weg = (const float4*)We;
        float4* Wesv = (float4*)Wes;
        #pragma unroll
        for (int i = tid; i < (D_EDGE * D_OUT) / 4; i += REL_THREADS)
            Wesv[i] = Weg[i];
    }

    const int warp = tid >> 5;
    const int lane = tid & 31;
    const int r0 = warp * 8;                    // 8 warps * 8 edges = 64
    const ulonglong2* Wv = (const ulonglong2*)Wes;

    const int ntiles = (E + REL_TILE - 1) / REL_TILE;

    for (int t = blockIdx.x; t < ntiles; t += gridDim.x) {
        const int e0 = t * REL_TILE;
        __syncthreads();   // smem reuse vs previous tile readers

        {
            const float4* Xeg = (const float4*)(Xe + (size_t)e0 * D_EDGE);
            const int lim = (E - e0) * (D_EDGE / 4);
            float4* Xsv = (float4*)Xs;
            #pragma unroll
            for (int i = tid; i < REL_TILE * (D_EDGE / 4); i += REL_THREADS)
                Xsv[i] = (i < lim) ? Xeg[i] : make_float4(0.f, 0.f, 0.f, 0.f);
        }
        if (tid < REL_TILE) {
            int e = e0 + tid;
            Ss[tid] = (e < E) ? __ldg(&src[e]) : 0;
            Ds[tid] = (e < E) ? __ldg(&dst[e]) : 0;
        }
        __syncthreads();

        // Seed accumulators with gathered XW rows (MLP=8 per warp).
        ulonglong2 acc[8];
        #pragma unroll
        for (int r = 0; r < 8; r++) {
            int s = Ss[r0 + r];
            F4U2 g; g.f = __ldg((const float4*)(XW + (size_t)s * 128) + lane);
            acc[r] = g.u;
        }

        #pragma unroll
        for (int k4 = 0; k4 < D_EDGE / 4; k4++) {
            const int k0 = 4 * k4;
            ulonglong2 w0 = Wv[(k0 + 0) * 32 + lane];
            ulonglong2 w1 = Wv[(k0 + 1) * 32 + lane];
            ulonglong2 w2 = Wv[(k0 + 2) * 32 + lane];
            ulonglong2 w3 = Wv[(k0 + 3) * 32 + lane];
            #pragma unroll
            for (int r = 0; r < 8; r++) {
                float4 xv = *(const float4*)&Xs[(r0 + r) * D_EDGE + k0]; // LDS.128 bcast
                unsigned long long xa = pk2(xv.x);
                unsigned long long xb = pk2(xv.y);
                unsigned long long xc = pk2(xv.z);
                unsigned long long xd = pk2(xv.w);
                acc[r].x = fma2(xa, w0.x, acc[r].x);
                acc[r].y = fma2(xa, w0.y, acc[r].y);
                acc[r].x = fma2(xb, w1.x, acc[r].x);
                acc[r].y = fma2(xb, w1.y, acc[r].y);
                acc[r].x = fma2(xc, w2.x, acc[r].x);
                acc[r].y = fma2(xc, w2.y, acc[r].y);
                acc[r].x = fma2(xd, w3.x, acc[r].x);
                acc[r].y = fma2(xd, w3.y, acc[r].y);
            }
        }

        #pragma unroll
        for (int r = 0; r < 8; r++) {
            if (e0 + r0 + r < E) {
                F4U2 o; o.u = acc[r];
                float4 v = o.f;
                v.x = fmaxf(v.x, 0.f); v.y = fmaxf(v.y, 0.f);
                v.z = fmaxf(v.z, 0.f); v.w = fmaxf(v.w, 0.f);
                red_add_v4(out + (size_t)Ds[r0 + r] * 128 + 4 * lane, v);
            }
        }
    }
}

// ---------------------------------------------------------------------------
// kernel_launch (metadata order unchanged)
// ---------------------------------------------------------------------------
extern "C" void kernel_launch(void* const* d_in, const int* in_sizes, int n_in,
                              void* d_out, int out_size)
{
    const float* X_user   = (const float*)d_in[0];
    const float* X_item   = (const float*)d_in[1];
    const float* Xe_ui    = (const float*)d_in[2];
    const float* Xe_iu    = (const float*)d_in[3];
    const float* W_src_ui = (const float*)d_in[4];
    const float* W_edge_ui= (const float*)d_in[5];
    const float* b_ui     = (const float*)d_in[6];
    const float* W_src_iu = (const float*)d_in[7];
    const float* W_edge_iu= (const float*)d_in[8];
    const float* b_iu     = (const float*)d_in[9];
    const float* Wl_user  = (const float*)d_in[10];
    const float* bl_user  = (const float*)d_in[11];
    const float* Wl_item  = (const float*)d_in[12];
    const float* bl_item  = (const float*)d_in[13];
    const int*   src_ui   = (const int*)d_in[14];
    const int*   dst_ui   = (const int*)d_in[15];
    const int*   src_iu   = (const int*)d_in[16];
    const int*   dst_iu   = (const int*)d_in[17];

    const int n_user = in_sizes[0] / D_IN;
    const int n_item = in_sizes[1] / D_IN;
    const int E      = in_sizes[14];

    float* H_user = (float*)d_out;
    float* H_item = (float*)d_out + (size_t)n_user * D_OUT;

    void* p_xwu = nullptr; void* p_xwi = nullptr;
    cudaGetSymbolAddress(&p_xwu, g_xwu);
    cudaGetSymbolAddress(&p_xwi, g_xwi);
    float* xwu = (float*)p_xwu;
    float* xwi = (float*)p_xwi;

    cudaFuncSetAttribute(node_kernel,
                         cudaFuncAttributeMaxDynamicSharedMemorySize,
                         NODE_SMEM_BYTES);

    // Persistent grids: 148 blocks per GEMM (y in {0,1}) -> 2 blocks/SM.
    dim3 gnode(148, 2);

    node_kernel<<<gnode, NODE_THREADS, NODE_SMEM_BYTES>>>(
        X_user, W_src_ui, b_ui, xwu, Wl_user, bl_user, H_user, n_user);

    node_kernel<<<gnode, NODE_THREADS, NODE_SMEM_BYTES>>>(
        X_item, W_src_iu, b_iu, xwi, Wl_item, bl_item, H_item, n_item);

    const int rel_grid = 148 * 3;
    rel_kernel<<<rel_grid, REL_THREADS>>>(xwu, Xe_ui, src_ui, dst_ui, W_edge_ui, H_item, E);
    rel_kernel<<<rel_grid, REL_THREADS>>>(xwi, Xe_iu, src_iu, dst_iu, W_edge_iu, H_user, E);
}